// round 10
// baseline (speedup 1.0000x reference)
#include <cuda_runtime.h>
#include <cstddef>

#define F 32
#define P 16

// Flag written by the dtype-detection prepass: 1 if idx/widx are int64, 0 if int32.
__device__ unsigned g_is64;

// jax silently downgrades int64->int32 when x64 is disabled, so the stored dtype
// of idx/widx is environment-dependent. Indices are < 2*M = 400000 < 2^31, so if
// the buffer is int64 every odd 32-bit word (the high half) is exactly 0.
// P(false positive | int32 data) ~ (2.5e-6)^64 ~ 0. Deterministic per input.
__global__ void detect_dtype_kernel(const unsigned* __restrict__ raw) {
    if (threadIdx.x == 0 && blockIdx.x == 0) {
        unsigned acc = 0u;
        #pragma unroll
        for (int i = 0; i < 64; ++i) acc |= raw[2 * i + 1];
        g_is64 = (acc == 0u) ? 1u : 0u;
    }
}

// 4 neurons per warp, 8 lanes per neuron, float4 per lane (proven R4 layout),
// but the per-step (idx,w) broadcast is ONE LDS.128 per TWO p-steps from a
// warp-private smem stage (synced with __syncwarp only), replacing 4 SHFLs.
// Mainloop crossbar wavefronts/warp: 64 gathers (floor) + 8 LDS vs 64 + 32.
//
// smem layout per warp: 4 neurons x 9 int4 (8 pair-chunks + 1 pad) -> 144B
// stride per neuron; the 4 groups' LDS.128 addresses land on distinct banks.
#define N4_PER_NEURON 9
#define N4_PER_WARP   (4 * N4_PER_NEURON)

__global__ __launch_bounds__(256)
void linear_gather_kernel(const float* __restrict__ values0,
                          const float* __restrict__ values1,
                          const float* __restrict__ w_table,
                          const void*  __restrict__ idx_raw,
                          const void*  __restrict__ widx_raw,
                          float* __restrict__ out,
                          int N, int M) {
    __shared__ int4 s_pairs[8 * N4_PER_WARP];   // 8 warps x 576B = 4.5KB

    const unsigned is64 = g_is64;
    const int lane = threadIdx.x & 31;
    const int wl   = threadIdx.x >> 5;          // warp in block
    const int nb   = blockIdx.x * 32;           // block's first neuron
    if (nb >= N) return;

    // ---- warp-private stage: thread t packs steps (2t, 2t+1) of neuron t>>3 ----
    {
        const int ln    = lane >> 3;            // local neuron 0..3
        const int halfp = lane & 7;             // 16B chunk: steps 2*halfp, 2*halfp+1
        int sn = nb + wl * 4 + ln;
        if (sn >= N) sn = N - 1;                // clamp (output predicated later)
        int i0, i1;
        long long wrow;
        if (is64) {
            const longlong2 L =
                ((const longlong2*)idx_raw)[(size_t)sn * (P / 2) + halfp];
            i0 = (int)L.x; i1 = (int)L.y;
            wrow = ((const long long*)widx_raw)[sn];
        } else {
            const int2 L = ((const int2*)idx_raw)[(size_t)sn * (P / 2) + halfp];
            i0 = L.x; i1 = L.y;
            wrow = ((const int*)widx_raw)[sn];
        }
        const float2 w2 = ((const float2*)(w_table + (size_t)wrow * P))[halfp];
        s_pairs[wl * N4_PER_WARP + ln * N4_PER_NEURON + halfp] =
            make_int4(i0, __float_as_int(w2.x), i1, __float_as_int(w2.y));
    }
    __syncwarp();

    // ---- mainloop ----
    const int grp = lane >> 3;                  // neuron group within warp
    const int sub = lane & 7;                   // lane within group (4 feature cols)
    int n = nb + wl * 4 + grp;
    const bool valid = (n < N);
    if (!valid) n = N - 1;

    const float* __restrict__ base0 = values0 + sub * 4;
    const float* __restrict__ base1 = values1 + sub * 4 - (size_t)M * F;
    const int4* __restrict__ sp =
        s_pairs + wl * N4_PER_WARP + grp * N4_PER_NEURON;

    float4 acc = make_float4(0.f, 0.f, 0.f, 0.f);

    #pragma unroll
    for (int q = 0; q < P / 2; ++q) {
        const int4 pr = sp[q];                  // (i0, w0, i1, w1): 1 wavefront
        const int   ip0 = pr.x, ip1 = pr.z;
        const float wp0 = __int_as_float(pr.y);
        const float wp1 = __int_as_float(pr.w);

        const float* s0 = (ip0 < M) ? base0 : base1;
        const float* s1 = (ip1 < M) ? base0 : base1;
        const float4 v0 = __ldg((const float4*)(s0 + (size_t)ip0 * F));
        const float4 v1 = __ldg((const float4*)(s1 + (size_t)ip1 * F));

        acc.x = fmaf(wp0, v0.x, acc.x);
        acc.y = fmaf(wp0, v0.y, acc.y);
        acc.z = fmaf(wp0, v0.z, acc.z);
        acc.w = fmaf(wp0, v0.w, acc.w);
        acc.x = fmaf(wp1, v1.x, acc.x);
        acc.y = fmaf(wp1, v1.y, acc.y);
        acc.z = fmaf(wp1, v1.z, acc.z);
        acc.w = fmaf(wp1, v1.w, acc.w);
    }

    if (valid)
        ((float4*)out)[(size_t)n * (F / 4) + sub] = acc;
}

extern "C" void kernel_launch(void* const* d_in, const int* in_sizes, int n_in,
                              void* d_out, int out_size) {
    // metadata order: values0 [M,F] f32, values1 [M,F] f32, w_table [K,P] f32,
    //                 idx [N,P] int64/int32, widx [N] int64/int32
    const float* values0 = (const float*)d_in[0];
    const float* values1 = (const float*)d_in[1];
    const float* w_table = (const float*)d_in[2];
    const void*  idx     = d_in[3];
    const void*  widx    = d_in[4];
    float* out = (float*)d_out;

    const int M = in_sizes[0] / F;   // rows per source layer
    const int N = in_sizes[4];       // output neurons (widx element count)

    detect_dtype_kernel<<<1, 32>>>((const unsigned*)idx);

    const int blocks = (N + 31) / 32;            // 32 neurons per 256-thread block
    linear_gather_kernel<<<blocks, 256>>>(values0, values1, w_table,
                                          idx, widx, out, N, M);
}

// round 11
// speedup vs baseline: 1.0829x; 1.0829x over previous
#include <cuda_runtime.h>
#include <cstddef>

#define F 32
#define P 16

// Flag written by the dtype-detection prepass: 1 if idx/widx are int64, 0 if int32.
__device__ unsigned g_is64;

// jax silently downgrades int64->int32 when x64 is disabled, so the stored dtype
// of idx/widx is environment-dependent. Indices are < 2*M = 400000 < 2^31, so if
// the buffer is int64 every odd 32-bit word (the high half) is exactly 0.
// P(false positive | int32 data) ~ (2.5e-6)^64 ~ 0. Deterministic per input.
__global__ void detect_dtype_kernel(const unsigned* __restrict__ raw) {
    if (threadIdx.x == 0 && blockIdx.x == 0) {
        unsigned acc = 0u;
        #pragma unroll
        for (int i = 0; i < 64; ++i) acc |= raw[2 * i + 1];
        g_is64 = (acc == 0u) ? 1u : 0u;
    }
}

// 4 neurons per warp, 8 lanes per neuron, float4 per lane; (idx,w) broadcast via
// warp-private smem stage (1 LDS.128 per 2 p-steps, replacing 4 SHFLs).
// R10 proved this cuts L1 busy ~12% but lost occupancy (39 regs -> 6 blocks/SM).
// This round pins 8 blocks/SM via __launch_bounds__(256, 8) (32-reg cap) and
// trims live state (single pool base + conditional delta, late n/valid).
#define N4_PER_NEURON 9   // 8 pair-chunks + 1 pad (144B stride -> distinct banks)
#define N4_PER_WARP   (4 * N4_PER_NEURON)

__global__ __launch_bounds__(256, 8)
void linear_gather_kernel(const float* __restrict__ values0,
                          const float* __restrict__ values1,
                          const float* __restrict__ w_table,
                          const void*  __restrict__ idx_raw,
                          const void*  __restrict__ widx_raw,
                          float* __restrict__ out,
                          int N, int M) {
    __shared__ int4 s_pairs[8 * N4_PER_WARP];   // 8 warps x 576B = 4.5KB

    const int lane = threadIdx.x & 31;
    const int wl   = threadIdx.x >> 5;          // warp in block
    const int nb   = blockIdx.x * 32;           // block's first neuron
    if (nb >= N) return;

    // ---- warp-private stage: thread packs steps (2h, 2h+1) of neuron lane>>3 ----
    {
        const int ln    = lane >> 3;            // local neuron 0..3
        const int halfp = lane & 7;             // 16B chunk: steps 2h, 2h+1
        int sn = nb + wl * 4 + ln;
        if (sn >= N) sn = N - 1;                // clamp (output predicated later)
        int i0, i1;
        long long wrow;
        if (g_is64) {
            const longlong2 L =
                ((const longlong2*)idx_raw)[(size_t)sn * (P / 2) + halfp];
            i0 = (int)L.x; i1 = (int)L.y;
            wrow = ((const long long*)widx_raw)[sn];
        } else {
            const int2 L = ((const int2*)idx_raw)[(size_t)sn * (P / 2) + halfp];
            i0 = L.x; i1 = L.y;
            wrow = ((const int*)widx_raw)[sn];
        }
        const float2 w2 = ((const float2*)(w_table + (size_t)wrow * P))[halfp];
        s_pairs[wl * N4_PER_WARP + ln * N4_PER_NEURON + halfp] =
            make_int4(i0, __float_as_int(w2.x), i1, __float_as_int(w2.y));
    }
    __syncwarp();

    // ---- mainloop ----
    const int sub = lane & 7;                   // lane within group (4 feature cols)
    // single base + conditional delta (saves one live 64-bit pointer)
    const float* __restrict__ base = values0 + sub * 4;
    const ptrdiff_t d1 = (values1 - values0) - (ptrdiff_t)M * F;
    const int4* __restrict__ sp =
        s_pairs + wl * N4_PER_WARP + (lane >> 3) * N4_PER_NEURON;

    float4 acc = make_float4(0.f, 0.f, 0.f, 0.f);

    #pragma unroll
    for (int q = 0; q < P / 2; ++q) {
        const int4 pr = sp[q];                  // (i0, w0, i1, w1): 1 wavefront
        const float4 v0 = __ldg((const float4*)(
            base + (size_t)pr.x * F + ((pr.x < M) ? 0 : d1)));
        const float4 v1 = __ldg((const float4*)(
            base + (size_t)pr.z * F + ((pr.z < M) ? 0 : d1)));
        const float wp0 = __int_as_float(pr.y);
        const float wp1 = __int_as_float(pr.w);
        acc.x = fmaf(wp0, v0.x, acc.x);
        acc.y = fmaf(wp0, v0.y, acc.y);
        acc.z = fmaf(wp0, v0.z, acc.z);
        acc.w = fmaf(wp0, v0.w, acc.w);
        acc.x = fmaf(wp1, v1.x, acc.x);
        acc.y = fmaf(wp1, v1.y, acc.y);
        acc.z = fmaf(wp1, v1.z, acc.z);
        acc.w = fmaf(wp1, v1.w, acc.w);
    }

    const int n = nb + wl * 4 + (lane >> 3);
    if (n < N)
        ((float4*)out)[(size_t)n * (F / 4) + sub] = acc;
}

extern "C" void kernel_launch(void* const* d_in, const int* in_sizes, int n_in,
                              void* d_out, int out_size) {
    // metadata order: values0 [M,F] f32, values1 [M,F] f32, w_table [K,P] f32,
    //                 idx [N,P] int64/int32, widx [N] int64/int32
    const float* values0 = (const float*)d_in[0];
    const float* values1 = (const float*)d_in[1];
    const float* w_table = (const float*)d_in[2];
    const void*  idx     = d_in[3];
    const void*  widx    = d_in[4];
    float* out = (float*)d_out;

    const int M = in_sizes[0] / F;   // rows per source layer
    const int N = in_sizes[4];       // output neurons (widx element count)

    detect_dtype_kernel<<<1, 32>>>((const unsigned*)idx);

    const int blocks = (N + 31) / 32;            // 32 neurons per 256-thread block
    linear_gather_kernel<<<blocks, 256>>>(values0, values1, w_table,
                                          idx, widx, out, N, M);
}

// round 12
// speedup vs baseline: 1.2530x; 1.1571x over previous
#include <cuda_runtime.h>
#include <cstddef>

#define F 32
#define P 16

// 4 neurons per warp, 8 lanes per neuron, float4 (4 feature columns) per lane —
// the proven-fastest layout (at the L1tex gather+fill floor). dtype detection is
// inlined per-warp (ballot over 64 fixed odd words of idx; addresses identical
// across the grid -> L1/L2-hot), removing the separate detect kernel node.
//
// jax silently downgrades int64->int32 when x64 is disabled, so idx/widx dtype
// is environment-dependent. Indices are < 2*M = 400000 < 2^31, so if the buffer
// is int64 every odd 32-bit word is exactly 0.
// P(false positive | int32 data) ~ (2.5e-6)^64 ~ 0. Deterministic per input.
__global__ __launch_bounds__(256)
void linear_gather_kernel(const float* __restrict__ values0,
                          const float* __restrict__ values1,
                          const float* __restrict__ w_table,
                          const void*  __restrict__ idx_raw,
                          const void*  __restrict__ widx_raw,
                          float* __restrict__ out,
                          int N, int M) {
    const int lane = threadIdx.x & 31;

    // ---- per-warp dtype detect: no smem, no barrier, no extra kernel ----
    unsigned hi;
    {
        const unsigned* raw = (const unsigned*)idx_raw;
        hi = raw[2 * lane + 1] | raw[64 + 2 * lane + 1];
    }
    const unsigned is64 =
        (__ballot_sync(0xffffffffu, hi != 0u) == 0u) ? 1u : 0u;

    const int warp = (blockIdx.x * blockDim.x + threadIdx.x) >> 5;
    const int sub  = lane & 7;        // lane within the neuron's 8-lane group
    const int nb   = warp * 4;
    int n = nb + (lane >> 3);         // this group's neuron
    if (nb >= N) return;
    const bool valid = (n < N);
    if (!valid) n = N - 1;            // clamp for loads; store is predicated

    // ---- preload: 2 indices + 2 weights per lane (16 per 8-lane group) ----
    int ia, ib;                       // idx[n*16 + 2*sub], idx[n*16 + 2*sub+1]
    long long wrow;
    if (is64) {
        const longlong2 L =
            ((const longlong2*)idx_raw)[(size_t)n * (P / 2) + sub];
        ia = (int)L.x; ib = (int)L.y;
        wrow = ((const long long*)widx_raw)[n];
    } else {
        const int2 L = ((const int2*)idx_raw)[(size_t)n * (P / 2) + sub];
        ia = L.x; ib = L.y;
        wrow = ((const int*)widx_raw)[n];
    }
    const float2 w2 =
        ((const float2*)(w_table + (size_t)wrow * P))[sub];  // w[2sub], w[2sub+1]

    // Per-lane feature base pointers (sub*4 columns), values1 pre-shifted by -M rows
    const float* __restrict__ base0 = values0 + sub * 4;
    const float* __restrict__ base1 = values1 + sub * 4 - (size_t)M * F;

    float4 acc = make_float4(0.f, 0.f, 0.f, 0.f);

    #pragma unroll
    for (int p = 0; p < P; ++p) {
        // broadcast within the 8-lane partition; source lane p/2 is an immediate
        const int   ip = (p & 1) ? __shfl_sync(0xffffffffu, ib, p >> 1, 8)
                                 : __shfl_sync(0xffffffffu, ia, p >> 1, 8);
        const float wp = (p & 1) ? __shfl_sync(0xffffffffu, w2.y, p >> 1, 8)
                                 : __shfl_sync(0xffffffffu, w2.x, p >> 1, 8);
        const float* src = (ip < M) ? base0 : base1;
        const float4 v = __ldg((const float4*)(src + (size_t)ip * F));
        acc.x = fmaf(wp, v.x, acc.x);
        acc.y = fmaf(wp, v.y, acc.y);
        acc.z = fmaf(wp, v.z, acc.z);
        acc.w = fmaf(wp, v.w, acc.w);
    }

    if (valid)
        ((float4*)out)[(size_t)n * (F / 4) + sub] = acc;
}

extern "C" void kernel_launch(void* const* d_in, const int* in_sizes, int n_in,
                              void* d_out, int out_size) {
    // metadata order: values0 [M,F] f32, values1 [M,F] f32, w_table [K,P] f32,
    //                 idx [N,P] int64/int32, widx [N] int64/int32
    const float* values0 = (const float*)d_in[0];
    const float* values1 = (const float*)d_in[1];
    const float* w_table = (const float*)d_in[2];
    const void*  idx     = d_in[3];
    const void*  widx    = d_in[4];
    float* out = (float*)d_out;

    const int M = in_sizes[0] / F;   // rows per source layer
    const int N = in_sizes[4];       // output neurons (widx element count)

    const int threads = 256;                       // 8 warps = 32 neurons/block
    const int neurons_per_block = (threads / 32) * 4;
    const int blocks = (N + neurons_per_block - 1) / neurons_per_block;
    linear_gather_kernel<<<blocks, threads>>>(values0, values1, w_table,
                                              idx, widx, out, N, M);
}